// round 1
// baseline (speedup 1.0000x reference)
#include <cuda_runtime.h>
#include <cuda_bf16.h>

// Problem constants (fixed by setup_inputs)
#define T_TOK 2048
#define NEXP  8
#define HD    1024
#define ID    4096
#define TOPK  2
#define NSLOT (T_TOK * TOPK)   // 4096 total assignments, always

// ---------------- scratch (static device globals; no allocation) -----------
__device__ int   g_topk_e[NSLOT];
__device__ float g_topk_w[NSLOT];
__device__ int   g_counts[NEXP];
__device__ int   g_base[NEXP];
__device__ int   g_cursor[NEXP];
__device__ int   g_slot_tok[NSLOT];
__device__ float g_slot_w[NSLOT];
__device__ int   g_token_slot[NSLOT];
__device__ float g_h[(size_t)NSLOT * 2 * ID];   // 4096 x 8192 = 134 MB
__device__ float g_act[(size_t)NSLOT * ID];     // 4096 x 4096 = 67 MB
__device__ float g_outslot[(size_t)NSLOT * HD]; // 4096 x 1024 = 17 MB

// ---------------- routing ---------------------------------------------------
__global__ void k_init() {
    if (threadIdx.x < NEXP) g_counts[threadIdx.x] = 0;
}

__global__ void k_router(const float* __restrict__ logits) {
    int t = blockIdx.x * blockDim.x + threadIdx.x;
    if (t >= T_TOK) return;
    float l[NEXP];
#pragma unroll
    for (int e = 0; e < NEXP; e++) l[e] = logits[t * NEXP + e];
    int i1 = 0; float m1 = l[0];
    int i2 = -1; float m2 = -3.0e38f;
#pragma unroll
    for (int e = 1; e < NEXP; e++) {
        if (l[e] > m1) { m2 = m1; i2 = i1; m1 = l[e]; i1 = e; }
        else if (l[e] > m2) { m2 = l[e]; i2 = e; }
    }
    // softmax -> top2 -> renormalize == softmax over the two top logits
    float r  = expf(m2 - m1);
    float w1 = 1.0f / (1.0f + r);
    float w2 = r * w1;
    g_topk_e[t * 2 + 0] = i1;
    g_topk_e[t * 2 + 1] = i2;
    g_topk_w[t * 2 + 0] = w1;
    g_topk_w[t * 2 + 1] = w2;
    atomicAdd(&g_counts[i1], 1);
    atomicAdd(&g_counts[i2], 1);
}

__global__ void k_scan() {
    if (threadIdx.x == 0 && blockIdx.x == 0) {
        int acc = 0;
        for (int e = 0; e < NEXP; e++) {
            g_base[e]   = acc;
            g_cursor[e] = acc;
            acc += g_counts[e];
        }
    }
}

__global__ void k_assign() {
    int t = blockIdx.x * blockDim.x + threadIdx.x;
    if (t >= T_TOK) return;
#pragma unroll
    for (int j = 0; j < TOPK; j++) {
        int e   = g_topk_e[t * 2 + j];
        int pos = atomicAdd(&g_cursor[e], 1);
        g_slot_tok[pos]        = t;
        g_slot_w[pos]          = g_topk_w[t * 2 + j];
        g_token_slot[t * 2 + j] = pos;
    }
}

// ---------------- GEMM1: h[slot, 0:8192] = x[tok] @ dequant(W13[e]) --------
// BM=128, BN=128, BK=16, 256 threads, 8x8 per thread.
#define BM 128
#define BN 128
#define BK 16

__global__ __launch_bounds__(256, 2)
void k_gemm1(const float* __restrict__ x,
             const int*   __restrict__ qw,   // (E, HD/8, 2*ID)
             const float* __restrict__ sc,   // (E, HD/128, 2*ID)
             const int*   __restrict__ gix)  // (E, HD)
{
    const int e  = blockIdx.z;
    const int m0 = blockIdx.y * BM;
    const int n0 = blockIdx.x * BN;
    const int cnt = g_counts[e];
    if (m0 >= cnt) return;
    const int base = g_base[e];

    __shared__ float As[BK][BM + 4];
    __shared__ float Bs[BK][BN];
    __shared__ int   toksh[BM];

    const int tid = threadIdx.x;
    const int ty  = tid >> 4;   // 0..15
    const int tx  = tid & 15;   // 0..15

    if (tid < BM) {
        int m = m0 + tid;
        toksh[tid] = (m < cnt) ? g_slot_tok[base + m] : -1;
    }

    const int*   qwe = qw  + (size_t)e * (HD / 8) * (2 * ID);
    const float* sce = sc  + (size_t)e * (HD / 128) * (2 * ID);
    const int*   ge  = gix + e * HD;

    float acc[8][8];
#pragma unroll
    for (int i = 0; i < 8; i++)
#pragma unroll
        for (int j = 0; j < 8; j++) acc[i][j] = 0.0f;

    for (int k0 = 0; k0 < HD; k0 += BK) {
        __syncthreads();
        // A tile: 128 rows x 16 k (gathered tokens)
#pragma unroll
        for (int i = 0; i < 8; i++) {
            int idx = tid + i * 256;
            int row = idx >> 4;
            int kk  = idx & 15;
            int tok = toksh[row];
            As[kk][row] = (tok >= 0) ? x[(size_t)tok * HD + k0 + kk] : 0.0f;
        }
        // B tile: 16 k x 128 n, dequant int4 * scale[g_idx[k]]
#pragma unroll
        for (int i = 0; i < 8; i++) {
            int idx = tid + i * 256;
            int kk  = idx >> 7;
            int nn  = idx & 127;
            int k   = k0 + kk;
            int q   = qwe[(size_t)(k >> 3) * (2 * ID) + n0 + nn];
            int nib = (q >> ((k & 7) * 4)) & 15;
            float s = sce[(size_t)ge[k] * (2 * ID) + n0 + nn];
            Bs[kk][nn] = (float)(nib - 8) * s;
        }
        __syncthreads();
#pragma unroll
        for (int kk = 0; kk < BK; kk++) {
            float4 a0 = *(const float4*)&As[kk][ty * 8];
            float4 a1 = *(const float4*)&As[kk][ty * 8 + 4];
            float4 b0 = *(const float4*)&Bs[kk][tx * 8];
            float4 b1 = *(const float4*)&Bs[kk][tx * 8 + 4];
            float a[8] = {a0.x, a0.y, a0.z, a0.w, a1.x, a1.y, a1.z, a1.w};
            float b[8] = {b0.x, b0.y, b0.z, b0.w, b1.x, b1.y, b1.z, b1.w};
#pragma unroll
            for (int i = 0; i < 8; i++)
#pragma unroll
                for (int j = 0; j < 8; j++) acc[i][j] = fmaf(a[i], b[j], acc[i][j]);
        }
    }

#pragma unroll
    for (int i = 0; i < 8; i++) {
        int m = m0 + ty * 8 + i;
        if (m < cnt) {
            size_t ro = (size_t)(base + m) * (2 * ID) + n0 + tx * 8;
            *(float4*)&g_h[ro]     = make_float4(acc[i][0], acc[i][1], acc[i][2], acc[i][3]);
            *(float4*)&g_h[ro + 4] = make_float4(acc[i][4], acc[i][5], acc[i][6], acc[i][7]);
        }
    }
}

// ---------------- activation: act = silu(gate) * up ------------------------
__global__ void k_act() {
    int s = blockIdx.y;
    int i = blockIdx.x * 256 + threadIdx.x;
    float g = g_h[(size_t)s * (2 * ID) + i];
    float u = g_h[(size_t)s * (2 * ID) + ID + i];
    g_act[(size_t)s * ID + i] = g / (1.0f + expf(-g)) * u;
}

// ---------------- GEMM2: outslot[slot] = w_slot * (act[slot] @ dequant(W2[e]))
__global__ __launch_bounds__(256, 2)
void k_gemm2(const int*   __restrict__ qw,   // (E, ID/8, HD)
             const float* __restrict__ sc,   // (E, ID/128, HD)
             const int*   __restrict__ gix)  // (E, ID)
{
    const int e  = blockIdx.z;
    const int m0 = blockIdx.y * BM;
    const int n0 = blockIdx.x * BN;
    const int cnt = g_counts[e];
    if (m0 >= cnt) return;
    const int base = g_base[e];

    __shared__ float As[BK][BM + 4];
    __shared__ float Bs[BK][BN];

    const int tid = threadIdx.x;
    const int ty  = tid >> 4;
    const int tx  = tid & 15;

    const int*   qwe = qw  + (size_t)e * (ID / 8) * HD;
    const float* sce = sc  + (size_t)e * (ID / 128) * HD;
    const int*   ge  = gix + e * ID;

    float acc[8][8];
#pragma unroll
    for (int i = 0; i < 8; i++)
#pragma unroll
        for (int j = 0; j < 8; j++) acc[i][j] = 0.0f;

    for (int k0 = 0; k0 < ID; k0 += BK) {
        __syncthreads();
#pragma unroll
        for (int i = 0; i < 8; i++) {
            int idx = tid + i * 256;
            int row = idx >> 4;
            int kk  = idx & 15;
            int m   = m0 + row;
            As[kk][row] = (m < cnt) ? g_act[(size_t)(base + m) * ID + k0 + kk] : 0.0f;
        }
#pragma unroll
        for (int i = 0; i < 8; i++) {
            int idx = tid + i * 256;
            int kk  = idx >> 7;
            int nn  = idx & 127;
            int k   = k0 + kk;
            int q   = qwe[(size_t)(k >> 3) * HD + n0 + nn];
            int nib = (q >> ((k & 7) * 4)) & 15;
            float s = sce[(size_t)ge[k] * HD + n0 + nn];
            Bs[kk][nn] = (float)(nib - 8) * s;
        }
        __syncthreads();
#pragma unroll
        for (int kk = 0; kk < BK; kk++) {
            float4 a0 = *(const float4*)&As[kk][ty * 8];
            float4 a1 = *(const float4*)&As[kk][ty * 8 + 4];
            float4 b0 = *(const float4*)&Bs[kk][tx * 8];
            float4 b1 = *(const float4*)&Bs[kk][tx * 8 + 4];
            float a[8] = {a0.x, a0.y, a0.z, a0.w, a1.x, a1.y, a1.z, a1.w};
            float b[8] = {b0.x, b0.y, b0.z, b0.w, b1.x, b1.y, b1.z, b1.w};
#pragma unroll
            for (int i = 0; i < 8; i++)
#pragma unroll
                for (int j = 0; j < 8; j++) acc[i][j] = fmaf(a[i], b[j], acc[i][j]);
        }
    }

#pragma unroll
    for (int i = 0; i < 8; i++) {
        int m = m0 + ty * 8 + i;
        if (m < cnt) {
            float w = g_slot_w[base + m];
            size_t ro = (size_t)(base + m) * HD + n0 + tx * 8;
            *(float4*)&g_outslot[ro] = make_float4(acc[i][0] * w, acc[i][1] * w,
                                                   acc[i][2] * w, acc[i][3] * w);
            *(float4*)&g_outslot[ro + 4] = make_float4(acc[i][4] * w, acc[i][5] * w,
                                                       acc[i][6] * w, acc[i][7] * w);
        }
    }
}

// ---------------- combine: out[t] = outslot[s0] + outslot[s1] --------------
__global__ void k_combine(float* __restrict__ out) {
    int t = blockIdx.y;
    int n = blockIdx.x * 256 + threadIdx.x;
    int s0 = g_token_slot[t * 2 + 0];
    int s1 = g_token_slot[t * 2 + 1];
    out[(size_t)t * HD + n] = g_outslot[(size_t)s0 * HD + n] +
                              g_outslot[(size_t)s1 * HD + n];
}

// ---------------- launch ----------------------------------------------------
extern "C" void kernel_launch(void* const* d_in, const int* in_sizes, int n_in,
                              void* d_out, int out_size) {
    const float* x      = (const float*)d_in[0];
    const float* logits = (const float*)d_in[1];
    const int*   w13_q  = (const int*)  d_in[2];
    const int*   w2_q   = (const int*)  d_in[3];
    const float* w13_s  = (const float*)d_in[4];
    const float* w2_s   = (const float*)d_in[5];
    const int*   w13_g  = (const int*)  d_in[6];
    const int*   w2_g   = (const int*)  d_in[7];
    float* out = (float*)d_out;
    (void)in_sizes; (void)n_in; (void)out_size;

    k_init<<<1, 32>>>();
    k_router<<<(T_TOK + 255) / 256, 256>>>(logits);
    k_scan<<<1, 32>>>();
    k_assign<<<(T_TOK + 255) / 256, 256>>>();

    // GEMM1: N=8192 -> 64 n-tiles, M worst-case 2048 -> 16 m-tiles, E=8
    dim3 g1(2 * ID / BN, (T_TOK + BM - 1) / BM, NEXP);
    k_gemm1<<<g1, 256>>>(x, w13_q, w13_s, w13_g);

    dim3 ga(ID / 256, NSLOT);
    k_act<<<ga, 256>>>();

    // GEMM2: N=1024 -> 8 n-tiles
    dim3 g2(HD / BN, (T_TOK + BM - 1) / BM, NEXP);
    k_gemm2<<<g2, 256>>>(w2_q, w2_s, w2_g);

    dim3 gc(HD / 256, T_TOK);
    k_combine<<<gc, 256>>>(out);
}